// round 3
// baseline (speedup 1.0000x reference)
#include <cuda_runtime.h>
#include <math_constants.h>

#define MAXB 256
#define LUTN 2048
#define INF_BITS 0x7F800000u

// Scratch (no allocations allowed — __device__ globals).
// g_tmax_bits: only ever atomicMax'd with the same values each call -> idempotent,
// never reset (avoids ordering race with block 0's prep inside the fused K1).
__device__ unsigned       g_tmax_bits = 0u;
__device__ float          g_bins_sorted[MAXB];
__device__ unsigned short g_lut[LUTN];
__device__ unsigned       g_cand_below[MAXB];  // min (bin - t), t <= bin, float bits
__device__ unsigned       g_cand_above[MAXB];  // min (t - bin), t >= bin, float bits
__device__ double         g_dir2;
__device__ unsigned       g_done;

// ---------------------------------------------------------------------------
// K1: block 0 -> bin prep (max, normalize, rank-sort, LUT, state init).
//     blocks 1..G-1 -> global max over targets (float4, bit atomicMax).
// ---------------------------------------------------------------------------
__global__ void k_prep_tmax(const float* __restrict__ bins, int nb,
                            const float* __restrict__ tgt, int n) {
    int tid = threadIdx.x;

    if (blockIdx.x == 0) {
        __shared__ float sv[MAXB];
        __shared__ float ss[MAXB];
        __shared__ float smax[256];

        float m = -CUDART_INF_F;
        for (int i = tid; i < nb; i += 256) {
            float v = bins[i];
            sv[i] = v;
            m = fmaxf(m, v);
        }
        smax[tid] = m;
        __syncthreads();
        for (int s = 128; s > 0; s >>= 1) {
            if (tid < s) smax[tid] = fmaxf(smax[tid], smax[tid + s]);
            __syncthreads();
        }
        float inv_bmax = 1.0f / smax[0];
        __syncthreads();

        for (int i = tid; i < nb; i += 256) sv[i] = sv[i] * inv_bmax;
        __syncthreads();

        // Rank sort (nb<=256 -> 256 compares per element).
        for (int i = tid; i < nb; i += 256) {
            float v = sv[i];
            int rank = 0;
            for (int j = 0; j < nb; j++) {
                float u = sv[j];
                rank += (u < v) || (u == v && j < i);
            }
            ss[rank] = v;
        }
        __syncthreads();

        for (int i = tid; i < nb; i += 256) g_bins_sorted[i] = ss[i];

        // LUT: lut[g] = count of bins with value < g/LUTN (lower bound of cell edge).
        for (int g = tid; g < LUTN; g += 256) {
            float edge = (float)g * (1.0f / LUTN);
            int lo = 0, hi = nb;
            while (lo < hi) {
                int mid = (lo + hi) >> 1;
                if (ss[mid] < edge) lo = mid + 1; else hi = mid;
            }
            g_lut[g] = (unsigned short)lo;
        }

        for (int i = tid; i < nb; i += 256) {
            g_cand_below[i] = INF_BITS;
            g_cand_above[i] = INF_BITS;
        }
        if (tid == 0) { g_dir2 = 0.0; g_done = 0u; }
    } else {
        // target max
        int nblk = gridDim.x - 1;
        int bid  = blockIdx.x - 1;
        int stride = nblk * 256;
        float m = 0.0f;

        const float4* t4 = (const float4*)tgt;
        int n4 = n >> 2;
        for (int i = bid * 256 + tid; i < n4; i += stride) {
            float4 v = t4[i];
            m = fmaxf(m, isfinite(v.x) ? v.x : 0.0f);
            m = fmaxf(m, isfinite(v.y) ? v.y : 0.0f);
            m = fmaxf(m, isfinite(v.z) ? v.z : 0.0f);
            m = fmaxf(m, isfinite(v.w) ? v.w : 0.0f);
        }
        for (int i = (n4 << 2) + bid * 256 + tid; i < n; i += stride) {
            float v = tgt[i];
            m = fmaxf(m, isfinite(v) ? v : 0.0f);
        }
        for (int o = 16; o; o >>= 1) m = fmaxf(m, __shfl_xor_sync(0xffffffffu, m, o));
        __shared__ float sm[8];
        if ((tid & 31) == 0) sm[tid >> 5] = m;
        __syncthreads();
        if (tid == 0) {
            float mm = sm[0];
            for (int i = 1; i < 8; i++) mm = fmaxf(mm, sm[i]);
            atomicMax(&g_tmax_bits, __float_as_uint(mm));  // positive floats: bit order
        }
    }
}

// ---------------------------------------------------------------------------
// K2: main pass + fused final (last block runs the prefix/suffix min-scans).
// Per target: LUT lookup + tiny linear walk instead of binary search.
// ---------------------------------------------------------------------------
__global__ void k_main_final(const float* __restrict__ tgt, int n, int nb,
                             float* __restrict__ out) {
    __shared__ float          sb[MAXB];
    __shared__ unsigned       sbel[MAXB];
    __shared__ unsigned       sabv[MAXB];
    __shared__ unsigned short slut[LUTN];
    __shared__ bool           amLast;

    int tid = threadIdx.x;
    for (int i = tid; i < nb; i += 256) {
        sb[i]   = g_bins_sorted[i];
        sbel[i] = INF_BITS;
        sabv[i] = INF_BITS;
    }
    for (int i = tid; i < LUTN; i += 256) slut[i] = g_lut[i];
    if (tid == 0) amLast = false;
    __syncthreads();

    float inv = 1.0f / __uint_as_float(g_tmax_bits);
    float acc = 0.0f;

    auto proc = [&](float raw) {
        float t = raw * inv;
        if (!isfinite(t)) return;
        int g = (int)(t * (float)LUTN);
        g = min(max(g, 0), LUTN - 1);
        int lo = slut[g];
        while (lo < nb && sb[lo] <= t) lo++;   // expected ~1 step
        while (lo > 0 && sb[lo - 1] > t) lo--; // float-rounding guard (expected 0)
        float best = CUDART_INF_F;
        if (lo > 0) {
            float d = t - sb[lo - 1];          // >= 0
            best = d;
            atomicMin(&sabv[lo - 1], __float_as_uint(d));
        }
        if (lo < nb) {
            float d = sb[lo] - t;              // > 0
            best = fminf(best, d);
            atomicMin(&sbel[lo], __float_as_uint(d));
        }
        if (isfinite(best)) acc += best * best;
    };

    {
        int stride = gridDim.x * 256;
        const float4* t4 = (const float4*)tgt;
        int n4 = n >> 2;
        for (int i = blockIdx.x * 256 + tid; i < n4; i += stride) {
            float4 v = t4[i];
            proc(v.x); proc(v.y); proc(v.z); proc(v.w);
        }
        for (int i = (n4 << 2) + blockIdx.x * 256 + tid; i < n; i += stride)
            proc(tgt[i]);
    }

    // dir2 block reduction -> double atomicAdd
    for (int o = 16; o; o >>= 1) acc += __shfl_xor_sync(0xffffffffu, acc, o);
    __shared__ float spart[8];
    if ((tid & 31) == 0) spart[tid >> 5] = acc;
    __syncthreads();
    if (tid == 0) {
        double s = 0.0;
        for (int i = 0; i < 8; i++) s += (double)spart[i];
        atomicAdd(&g_dir2, s);
    }

    // merge candidate mins to global
    for (int i = tid; i < nb; i += 256) {
        if (sbel[i] != INF_BITS) atomicMin(&g_cand_below[i], sbel[i]);
        if (sabv[i] != INF_BITS) atomicMin(&g_cand_above[i], sabv[i]);
    }

    // last-block-done: final scan on L2-hot data
    __threadfence();
    __syncthreads();
    if (tid == 0) {
        unsigned v = atomicAdd(&g_done, 1u);
        amLast = (v == gridDim.x - 1);
    }
    __syncthreads();
    if (!amLast) return;

    // Reuse sbel/sabv as float scan arrays.
    //   d_above[j] = min_{k>=j}(cand_above[k] + b[k]) - b[j]   (suffix min)
    //   d_below[j] = min_{k<=j}(cand_below[k] - b[k]) + b[j]   (prefix min)
    float* fA = (float*)sabv;
    float* fB = (float*)sbel;
    if (tid < nb) {
        float b  = sb[tid];
        float ca = __uint_as_float(((volatile unsigned*)g_cand_above)[tid]);
        float cb = __uint_as_float(((volatile unsigned*)g_cand_below)[tid]);
        fA[tid] = ca + b;
        fB[tid] = cb - b;
    }
    __syncthreads();

    for (int off = 1; off < nb; off <<= 1) {
        float a = CUDART_INF_F, bp = CUDART_INF_F;
        if (tid < nb) {
            if (tid + off < nb) a  = fA[tid + off];
            if (tid >= off)     bp = fB[tid - off];
        }
        __syncthreads();
        if (tid < nb) {
            fA[tid] = fminf(fA[tid], a);
            fB[tid] = fminf(fB[tid], bp);
        }
        __syncthreads();
    }

    double nnsq = 0.0;
    if (tid < nb) {
        float nn = fminf(fA[tid] - sb[tid], fB[tid] + sb[tid]);
        if (isfinite(nn)) nnsq = (double)nn * (double)nn;
    }
    for (int o = 16; o; o >>= 1) nnsq += __shfl_xor_sync(0xffffffffu, nnsq, o);
    __shared__ double sd[8];
    if ((tid & 31) == 0) sd[tid >> 5] = nnsq;
    __syncthreads();
    if (tid == 0) {
        double s = 0.0;
        for (int i = 0; i < 8; i++) s += sd[i];
        double d2 = *((volatile double*)&g_dir2);
        out[0] = (float)(s + d2);
    }
}

// ---------------------------------------------------------------------------
extern "C" void kernel_launch(void* const* d_in, const int* in_sizes, int n_in,
                              void* d_out, int out_size) {
    const float* tgt;
    const float* bins;
    int nT, nB;
    if (in_sizes[0] >= in_sizes[1]) {
        tgt = (const float*)d_in[0]; nT = in_sizes[0];
        bins = (const float*)d_in[1]; nB = in_sizes[1];
    } else {
        tgt = (const float*)d_in[1]; nT = in_sizes[1];
        bins = (const float*)d_in[0]; nB = in_sizes[0];
    }
    if (nB > MAXB) nB = MAXB;  // defensive; actual nB = 256

    int work_blocks = (nT + 1023) / 1024;      // ~4 elems/thread @256 thr
    if (work_blocks > 300) work_blocks = 300;
    if (work_blocks < 1)   work_blocks = 1;

    k_prep_tmax<<<work_blocks + 1, 256>>>(bins, nB, tgt, nT);
    k_main_final<<<work_blocks, 256>>>(tgt, nT, nB, (float*)d_out);
}

// round 4
// speedup vs baseline: 1.1486x; 1.1486x over previous
#include <cuda_runtime.h>
#include <math_constants.h>

#define MAXB 256
#define TPB  256
#define INF_BITS 0x7F800000u
#define MAXGRID 1100

// Persistent scratch (__device__ globals; no allocations allowed).
__device__ unsigned g_tmax_bits = 0u;     // idempotent across replays (never reset)
__device__ unsigned g_bar1 = 0u;          // reset by last block at end of each launch
__device__ unsigned g_done = 0u;          // reset by block 0 in phase 1
__device__ float    g_bins_sorted[MAXB];
__device__ unsigned g_cand_below[MAXB];   // re-INF'd by block 0 in phase 1
__device__ unsigned g_cand_above[MAXB];
__device__ double   g_part[MAXGRID];

__global__ __launch_bounds__(TPB)
void k_all(const float* __restrict__ bins, int nb,
           const float* __restrict__ tgt, int n,
           float* __restrict__ out) {
    __shared__ float    sb[MAXB];
    __shared__ unsigned sbel[MAXB];
    __shared__ unsigned sabv[MAXB];
    __shared__ float    red[TPB / 32];
    __shared__ bool     amLast;

    const int tid  = threadIdx.x;
    const int bid  = blockIdx.x;
    const int grid = gridDim.x;
    const int n4   = n >> 2;
    const int tailn = n - (n4 << 2);
    const bool reg_path = (grid * TPB >= n4);  // every thread owns <=1 float4

    // ---------------- Phase 1: target max (+ block 0: bin prep) -----------
    float4 v   = make_float4(0.f, 0.f, 0.f, 0.f);
    bool   have = false;
    float  tailv = 0.f;
    bool   havetail = false;
    float  m = 0.0f;

    if (reg_path) {
        int idx = bid * TPB + tid;
        if (idx < n4) { v = ((const float4*)tgt)[idx]; have = true; }
        if (have) {
            m = fmaxf(m, isfinite(v.x) ? v.x : 0.f);
            m = fmaxf(m, isfinite(v.y) ? v.y : 0.f);
            m = fmaxf(m, isfinite(v.z) ? v.z : 0.f);
            m = fmaxf(m, isfinite(v.w) ? v.w : 0.f);
        }
    } else {
        int stride = grid * TPB;
        const float4* t4 = (const float4*)tgt;
        for (int i = bid * TPB + tid; i < n4; i += stride) {
            float4 u = t4[i];
            m = fmaxf(m, isfinite(u.x) ? u.x : 0.f);
            m = fmaxf(m, isfinite(u.y) ? u.y : 0.f);
            m = fmaxf(m, isfinite(u.z) ? u.z : 0.f);
            m = fmaxf(m, isfinite(u.w) ? u.w : 0.f);
        }
    }
    if (bid == 0 && tid < tailn) {
        tailv = tgt[(n4 << 2) + tid];
        havetail = true;
        m = fmaxf(m, isfinite(tailv) ? tailv : 0.f);
    }

    for (int o = 16; o; o >>= 1) m = fmaxf(m, __shfl_xor_sync(0xffffffffu, m, o));
    if ((tid & 31) == 0) red[tid >> 5] = m;
    __syncthreads();
    if (tid == 0) {
        float mm = red[0];
        #pragma unroll
        for (int i = 1; i < TPB / 32; i++) mm = fmaxf(mm, red[i]);
        atomicMax(&g_tmax_bits, __float_as_uint(mm));  // positive floats: bit order
    }

    if (bid == 0) {
        // Bin prep: max, normalize, rank-sort into sb, publish to global.
        float* fraw = (float*)sbel;   // scratch
        __syncthreads();
        float bm = -CUDART_INF_F;
        for (int i = tid; i < nb; i += TPB) {
            float b = bins[i];
            fraw[i] = b;
            bm = fmaxf(bm, b);
        }
        for (int o = 16; o; o >>= 1) bm = fmaxf(bm, __shfl_xor_sync(0xffffffffu, bm, o));
        if ((tid & 31) == 0) red[tid >> 5] = bm;
        __syncthreads();
        float inv_bm = 1.0f / fmaxf(fmaxf(fmaxf(red[0], red[1]),
                                          fmaxf(red[2], red[3])),
                                    fmaxf(fmaxf(red[4], red[5]),
                                          fmaxf(red[6], red[7])));
        for (int i = tid; i < nb; i += TPB) fraw[i] *= inv_bm;
        __syncthreads();
        for (int i = tid; i < nb; i += TPB) {
            float val = fraw[i];
            int rank = 0;
            for (int j = 0; j < nb; j++) {
                float u = fraw[j];
                rank += (u < val) || (u == val && j < i);
            }
            sb[rank] = val;
        }
        __syncthreads();
        for (int i = tid; i < nb; i += TPB) {
            g_bins_sorted[i] = sb[i];
            g_cand_below[i]  = INF_BITS;
            g_cand_above[i]  = INF_BITS;
        }
        if (tid == 0) g_done = 0u;
    }

    // ---------------- Grid barrier ----------------------------------------
    if (tid == 0) {
        __threadfence();
        atomicAdd(&g_bar1, 1u);
        while (*(volatile unsigned*)&g_bar1 < (unsigned)grid) __nanosleep(64);
        __threadfence();
    }
    __syncthreads();

    // ---------------- Phase 2: main pass ----------------------------------
    if (bid != 0) {
        for (int i = tid; i < nb; i += TPB)
            sb[i] = *((volatile float*)&g_bins_sorted[i]);
    }
    for (int i = tid; i < nb; i += TPB) { sbel[i] = INF_BITS; sabv[i] = INF_BITS; }
    __syncthreads();

    const float inv = 1.0f / __uint_as_float(*(volatile unsigned*)&g_tmax_bits);
    float acc = 0.0f;

    auto proc = [&](float raw) {
        float t = raw * inv;
        if (!isfinite(t)) return;
        // upper_bound: number of bins <= t (branchless binary search)
        int lo = 0;
        #pragma unroll
        for (int step = 128; step; step >>= 1) {
            int cand = lo + step;
            if (cand <= nb && sb[cand - 1] <= t) lo = cand;
        }
        float best = CUDART_INF_F;
        if (lo > 0) {
            float d = t - sb[lo - 1];
            best = d;
            atomicMin(&sabv[lo - 1], __float_as_uint(d));
        }
        if (lo < nb) {
            float d = sb[lo] - t;
            best = fminf(best, d);
            atomicMin(&sbel[lo], __float_as_uint(d));
        }
        if (isfinite(best)) acc += best * best;
    };

    if (reg_path) {
        if (have) { proc(v.x); proc(v.y); proc(v.z); proc(v.w); }
    } else {
        int stride = grid * TPB;
        const float4* t4 = (const float4*)tgt;
        for (int i = bid * TPB + tid; i < n4; i += stride) {
            float4 u = t4[i];
            proc(u.x); proc(u.y); proc(u.z); proc(u.w);
        }
    }
    if (havetail) proc(tailv);

    // dir2 block partial -> g_part[bid] (no serialized atomics)
    for (int o = 16; o; o >>= 1) acc += __shfl_xor_sync(0xffffffffu, acc, o);
    if ((tid & 31) == 0) red[tid >> 5] = acc;
    __syncthreads();
    if (tid == 0) {
        double s = 0.0;
        #pragma unroll
        for (int i = 0; i < TPB / 32; i++) s += (double)red[i];
        g_part[bid] = s;
    }

    // merge candidate mins to global (spread addresses)
    for (int i = tid; i < nb; i += TPB) {
        if (sbel[i] != INF_BITS) atomicMin(&g_cand_below[i], sbel[i]);
        if (sabv[i] != INF_BITS) atomicMin(&g_cand_above[i], sabv[i]);
    }

    // ---------------- Last block: final scan + output ----------------------
    __threadfence();
    __syncthreads();
    if (tid == 0) amLast = (atomicAdd(&g_done, 1u) == (unsigned)(grid - 1));
    __syncthreads();
    if (!amLast) return;

    // d_above[j] = min_{k>=j}(cand_above[k]+b[k]) - b[j]  (suffix min)
    // d_below[j] = min_{k<=j}(cand_below[k]-b[k]) + b[j]  (prefix min)
    float* fA = (float*)sabv;
    float* fB = (float*)sbel;
    if (tid < nb) {
        float b  = sb[tid];
        float ca = __uint_as_float(*((volatile unsigned*)&g_cand_above[tid]));
        float cb = __uint_as_float(*((volatile unsigned*)&g_cand_below[tid]));
        fA[tid] = ca + b;
        fB[tid] = cb - b;
    }
    __syncthreads();
    for (int off = 1; off < nb; off <<= 1) {
        float a = CUDART_INF_F, bp = CUDART_INF_F;
        if (tid < nb) {
            if (tid + off < nb) a  = fA[tid + off];
            if (tid >= off)     bp = fB[tid - off];
        }
        __syncthreads();
        if (tid < nb) {
            fA[tid] = fminf(fA[tid], a);
            fB[tid] = fminf(fB[tid], bp);
        }
        __syncthreads();
    }

    double total = 0.0;
    if (tid < nb) {
        float nn = fminf(fA[tid] - sb[tid], fB[tid] + sb[tid]);
        if (isfinite(nn)) total = (double)nn * (double)nn;
    }
    // add dir2 partials (grid <= MAXGRID)
    for (int i = tid; i < grid; i += TPB) total += g_part[i];

    for (int o = 16; o; o >>= 1) total += __shfl_xor_sync(0xffffffffu, total, o);
    __shared__ double sd[TPB / 32];
    if ((tid & 31) == 0) sd[tid >> 5] = total;
    __syncthreads();
    if (tid == 0) {
        double s = 0.0;
        #pragma unroll
        for (int i = 0; i < TPB / 32; i++) s += sd[i];
        out[0] = (float)s;
        g_bar1 = 0u;   // reset for next replay (no one else reads it anymore)
    }
}

// ---------------------------------------------------------------------------
extern "C" void kernel_launch(void* const* d_in, const int* in_sizes, int n_in,
                              void* d_out, int out_size) {
    const float* tgt;
    const float* bins;
    int nT, nB;
    if (in_sizes[0] >= in_sizes[1]) {
        tgt = (const float*)d_in[0]; nT = in_sizes[0];
        bins = (const float*)d_in[1]; nB = in_sizes[1];
    } else {
        tgt = (const float*)d_in[1]; nT = in_sizes[1];
        bins = (const float*)d_in[0]; nB = in_sizes[0];
    }
    if (nB > MAXB) nB = MAXB;  // defensive; actual nB = 256

    int n4 = nT >> 2;
    int blocks = (n4 + TPB - 1) / TPB;   // one float4 per thread
    if (blocks < 1) blocks = 1;
    if (blocks > MAXGRID) blocks = MAXGRID;  // falls back to loop path

    k_all<<<blocks, TPB>>>(bins, nB, tgt, nT, (float*)d_out);
}